// round 16
// baseline (speedup 1.0000x reference)
#include <cuda_runtime.h>
#include <cuda_fp16.h>
#include <cstdint>

#define NSTEPS 64
#define NP1 65
#define B2 4096
#define TILE 64
#define THREADS 512
#define SPC 4
#define GROUPS (NSTEPS / SPC)     // 16
#define NTILES (B2 / TILE)        // 64

// ---- smem byte offsets ----
#define OFF_W2HI 0
#define OFF_W3HI 32768
#define OFF_A0H  65536
#define OFF_A0D  81920
#define OFF_A0E  98304
#define OFF_A1H  114688
#define OFF_A1D  131072
#define OFF_A1E  147456
#define OFF_B2   163840
#define OFF_B3   164352
#define OFF_B4   164864
#define OFF_SRED 165376
#define SMEM_BYTES 166912

#define IB2   (OFF_B2 >> 2)
#define IB3   (OFF_B3 >> 2)
#define IB4   (OFF_B4 >> 2)
#define ISRED (OFF_SRED >> 2)

__device__ float g_partial[GROUPS * B2];
__device__ float g_W4T[100 * 128];

static __device__ __forceinline__ float tanh_fast(float x) {
    float e = __expf(2.0f * x);
    return 1.0f - __fdividef(2.0f, e + 1.0f);
}
static __device__ __forceinline__ uint32_t swzb(uint32_t r, uint32_t cb) {
    return ((r << 8) + cb) ^ ((r & 7) << 4);
}
static __device__ __forceinline__ uint32_t packh2(float lo, float hi) {
    uint32_t r; asm("cvt.rn.f16x2.f32 %0,%1,%2;" : "=r"(r) : "f"(hi), "f"(lo)); return r;
}
static __device__ __forceinline__ void ldsm4(uint32_t* r, uint32_t a) {
    asm volatile("ldmatrix.sync.aligned.m8n8.x4.shared.b16 {%0,%1,%2,%3},[%4];"
        : "=r"(r[0]), "=r"(r[1]), "=r"(r[2]), "=r"(r[3]) : "r"(a));
}
static __device__ __forceinline__ void mma16816(float* d, const uint32_t* a, const uint32_t* b) {
    asm volatile("mma.sync.aligned.m16n8k16.row.col.f32.f16.f16.f32 "
        "{%0,%1,%2,%3},{%4,%5,%6,%7},{%8,%9},{%0,%1,%2,%3};"
        : "+f"(d[0]), "+f"(d[1]), "+f"(d[2]), "+f"(d[3])
        : "r"(a[0]), "r"(a[1]), "r"(a[2]), "r"(a[3]), "r"(b[0]), "r"(b[1]));
}
static __device__ __forceinline__ void chain(float z, float p, float q,
                                             float& h, float& d, float& e) {
    h = tanh_fast(z);
    float g = 1.0f - h * h;
    d = g * p;
    e = fmaf(g, q, -2.0f * h * d * p);
}
// group barrier: the 4 warps of one sample slab (one warp per SMSP), ids 1..4
static __device__ __forceinline__ void gbar(int slab) {
    asm volatile("bar.sync %0, 128;" :: "r"(slab + 1) : "memory");
}

__global__ void w4t_init(const float* __restrict__ W4) {
    int i = blockIdx.x * 256 + threadIdx.x;
    if (i < 12800) {
        int n = i >> 7, k = i & 127;
        g_W4T[i] = W4[k * 100 + n];
    }
}

// layer-1 forward-mode for one slab's 16 rows -> A0 (fp16, swizzled).
static __device__ __forceinline__ void layer1(
    char* smem, const float* __restrict__ ss,
    const float* __restrict__ W1, const float* __restrict__ b1,
    int tile, int m0, int gtid, int scol, float tk)
{
#pragma unroll
    for (int it = 0; it < 8; it++) {
        int i = gtid + it * 128;
        int r = m0 + (i >> 6), c0 = (i & 63) * 2;
        float s = __ldg(&ss[(tile * TILE + r) * NP1 + scol]);
        float2 w1s = __ldg((const float2*)&W1[c0]);
        float2 w1t = __ldg((const float2*)&W1[128 + c0]);
        float2 b1v = __ldg((const float2*)&b1[c0]);
        float z0 = fmaf(s, w1s.x, fmaf(tk, w1t.x, b1v.x));
        float z1 = fmaf(s, w1s.y, fmaf(tk, w1t.y, b1v.y));
        float h0 = tanh_fast(z0), h1 = tanh_fast(z1);
        float g0 = 1.f - h0 * h0, g1 = 1.f - h1 * h1;
        float d0 = g0 * w1s.x, d1 = g1 * w1s.y;
        float e0 = -2.f * h0 * d0 * w1s.x, e1 = -2.f * h1 * d1 * w1s.y;
        uint32_t o = swzb((uint32_t)r, (uint32_t)(c0 * 2));
        *(uint32_t*)(smem + OFF_A0H + o) = packh2(h0, h1);
        *(uint32_t*)(smem + OFF_A0D + o) = packh2(d0, d1);
        *(uint32_t*)(smem + OFF_A0E + o) = packh2(e0, e1);
    }
}

__global__ __launch_bounds__(THREADS, 1)
void bsde_main(const float* __restrict__ W1, const float* __restrict__ b1,
               const float* __restrict__ W2, const float* __restrict__ b2f,
               const float* __restrict__ W3, const float* __restrict__ b3f,
               const float* __restrict__ b4f,
               const int* __restrict__ sn, const float* __restrict__ ss,
               const float* __restrict__ sdB, const float* __restrict__ tptr)
{
    extern __shared__ char smem[];
    uint32_t sb = (uint32_t)__cvta_generic_to_shared(smem);
    float* smf = (float*)smem;
    const int tid = threadIdx.x;
    const int lane = tid & 31;
    const int w = tid >> 5;
    // TRANSPOSED mapping: slab spreads its 4 warps across the 4 SMSPs.
    const int slab = w >> 2;       // sample slab (m16)
    const int nq = w & 3;          // col quarter (n32) == SMSP id
    const int m0 = slab * 16;
    const int nbase = nq * 32;
    const int gtid = nq * 32 + lane;

    for (int i = tid; i < 128 * 128; i += THREADS) {
        int k = i >> 7, j = i & 127;
        uint32_t o = swzb((uint32_t)j, (uint32_t)(k * 2));
        *(__half*)(smem + OFF_W2HI + o) = __float2half_rn(W2[i]);
        *(__half*)(smem + OFF_W3HI + o) = __float2half_rn(W3[i]);
    }
    if (tid < 128) {
        smf[IB2 + tid] = b2f[tid];
        smf[IB3 + tid] = b3f[tid];
        smf[IB4 + tid] = (tid < 100) ? b4f[tid] : 0.0f;
    }

    const int tile = blockIdx.x & (NTILES - 1);
    const int grp = blockIdx.x >> 6;
    const int j0 = grp * SPC;
    const float t = *tptr;
    const float dt = t / (float)NSTEPS;
    const float halfdt = 0.5f * dt;
    float acc1 = 0.0f, acc2 = 0.0f;    // per-(row,nq) partials, combined ONCE at end

    const uint32_t rowA = (uint32_t)(m0 + (lane & 7) + ((lane >> 3) & 1) * 8);
    const uint32_t colA = (uint32_t)(((lane >> 4) & 1) * 16);
    const uint32_t rbA  = rowA << 8;
    const uint32_t xA   = (rowA & 7) << 4;
    const uint32_t rowB4 = (uint32_t)((lane & 7) + ((lane >> 4) & 1) * 8);
    const uint32_t colB4 = (uint32_t)(((lane >> 3) & 1) * 16);
    const uint32_t xB4   = (uint32_t)(lane & 7) << 4;

    const int r1 = m0 + (lane >> 2);
    const int r2 = r1 + 8;
    const int jc = 2 * (lane & 3);

    __syncthreads();   // weights + biases ready

    // prologue: layer-1 for first step
    {
        const float tk0 = (j0 == 0) ? t : (t - dt * (float)(j0 - 1));
        layer1(smem, ss, W1, b1, tile, m0, gtid, NSTEPS - j0, tk0);
    }
    gbar(slab);

    for (int jj = 0; jj < SPC; jj++) {
        const int j = j0 + jj;

        const float dB1 = sdB[(tile * TILE + r1) * NSTEPS + (NSTEPS - 1 - j)];
        const float dB2 = sdB[(tile * TILE + r2) * NSTEPS + (NSTEPS - 1 - j)];
        const int nb1 = sn[(tile * TILE + r1) * NP1 + (NSTEPS - j)];
        const int nb2 = sn[(tile * TILE + r2) * NP1 + (NSTEPS - j)];

        // ================= layer 2: A0 @ W2 -> A1 =================
        {
            float dz[2][8], dp[2][8], dq[2][8];
#pragma unroll
            for (int nt = 0; nt < 2; nt++) {
                const int j0c = nbase + nt * 16 + jc;
                float2 bj = *(const float2*)&smf[IB2 + j0c];
                float2 bj8 = *(const float2*)&smf[IB2 + j0c + 8];
                dz[nt][0] = bj.x; dz[nt][1] = bj.y; dz[nt][2] = bj.x; dz[nt][3] = bj.y;
                dz[nt][4] = bj8.x; dz[nt][5] = bj8.y; dz[nt][6] = bj8.x; dz[nt][7] = bj8.y;
#pragma unroll
                for (int e = 0; e < 8; e++) { dp[nt][e] = 0.f; dq[nt][e] = 0.f; }
            }
            const uint32_t aHb = sb + OFF_A0H + rbA, aDb = sb + OFF_A0D + rbA, aEb = sb + OFF_A0E + rbA;
            const uint32_t wBase = sb + OFF_W2HI + (((uint32_t)nbase + rowB4) << 8);
#pragma unroll
            for (int k = 0; k < 8; k++) {
                const uint32_t oA = (colA + 32u * k) ^ xA;
                const uint32_t oB = (colB4 + 32u * k) ^ xB4;
                uint32_t fa[4], fd[4], fe[4];
                ldsm4(fa, aHb + oA); ldsm4(fd, aDb + oA); ldsm4(fe, aEb + oA);
#pragma unroll
                for (int nt = 0; nt < 2; nt++) {
                    uint32_t bf[4];
                    ldsm4(bf, wBase + ((uint32_t)(nt * 16) << 8) + oB);
                    mma16816(dz[nt], fa, bf); mma16816(dz[nt] + 4, fa, bf + 2);
                    mma16816(dp[nt], fd, bf); mma16816(dp[nt] + 4, fd, bf + 2);
                    mma16816(dq[nt], fe, bf); mma16816(dq[nt] + 4, fe, bf + 2);
                }
            }
#pragma unroll
            for (int nt = 0; nt < 2; nt++) {
                const int j0c = nbase + nt * 16 + jc;
                float h[8], hd[8], he[8];
#pragma unroll
                for (int e = 0; e < 8; e++) chain(dz[nt][e], dp[nt][e], dq[nt][e], h[e], hd[e], he[e]);
                uint32_t o1 = swzb((uint32_t)r1, (uint32_t)(j0c * 2));
                uint32_t o2 = swzb((uint32_t)r2, (uint32_t)(j0c * 2));
                uint32_t o3 = swzb((uint32_t)r1, (uint32_t)((j0c + 8) * 2));
                uint32_t o4 = swzb((uint32_t)r2, (uint32_t)((j0c + 8) * 2));
                *(uint32_t*)(smem + OFF_A1H + o1) = packh2(h[0], h[1]);
                *(uint32_t*)(smem + OFF_A1H + o2) = packh2(h[2], h[3]);
                *(uint32_t*)(smem + OFF_A1H + o3) = packh2(h[4], h[5]);
                *(uint32_t*)(smem + OFF_A1H + o4) = packh2(h[6], h[7]);
                *(uint32_t*)(smem + OFF_A1D + o1) = packh2(hd[0], hd[1]);
                *(uint32_t*)(smem + OFF_A1D + o2) = packh2(hd[2], hd[3]);
                *(uint32_t*)(smem + OFF_A1D + o3) = packh2(hd[4], hd[5]);
                *(uint32_t*)(smem + OFF_A1D + o4) = packh2(hd[6], hd[7]);
                *(uint32_t*)(smem + OFF_A1E + o1) = packh2(he[0], he[1]);
                *(uint32_t*)(smem + OFF_A1E + o2) = packh2(he[2], he[3]);
                *(uint32_t*)(smem + OFF_A1E + o3) = packh2(he[4], he[5]);
                *(uint32_t*)(smem + OFF_A1E + o4) = packh2(he[6], he[7]);
            }
        }
        gbar(slab);      // A1 ready; A0 now dead -> safe to refill below

        // ================= layer 3 (A1 @ W3) + pipelined layer-1(j+1) + layer 4 =================
        {
            float dz[2][8], dp[2][8], dq[2][8];
#pragma unroll
            for (int nt = 0; nt < 2; nt++) {
                const int j0c = nbase + nt * 16 + jc;
                float2 bj = *(const float2*)&smf[IB3 + j0c];
                float2 bj8 = *(const float2*)&smf[IB3 + j0c + 8];
                dz[nt][0] = bj.x; dz[nt][1] = bj.y; dz[nt][2] = bj.x; dz[nt][3] = bj.y;
                dz[nt][4] = bj8.x; dz[nt][5] = bj8.y; dz[nt][6] = bj8.x; dz[nt][7] = bj8.y;
#pragma unroll
                for (int e = 0; e < 8; e++) { dp[nt][e] = 0.f; dq[nt][e] = 0.f; }
            }
            const uint32_t aHb = sb + OFF_A1H + rbA, aDb = sb + OFF_A1D + rbA, aEb = sb + OFF_A1E + rbA;
            const uint32_t wBase = sb + OFF_W3HI + (((uint32_t)nbase + rowB4) << 8);
#pragma unroll
            for (int k = 0; k < 8; k++) {
                const uint32_t oA = (colA + 32u * k) ^ xA;
                const uint32_t oB = (colB4 + 32u * k) ^ xB4;
                uint32_t fa[4], fd[4], fe[4];
                ldsm4(fa, aHb + oA); ldsm4(fd, aDb + oA); ldsm4(fe, aEb + oA);
#pragma unroll
                for (int nt = 0; nt < 2; nt++) {
                    uint32_t bf[4];
                    ldsm4(bf, wBase + ((uint32_t)(nt * 16) << 8) + oB);
                    mma16816(dz[nt], fa, bf); mma16816(dz[nt] + 4, fa, bf + 2);
                    mma16816(dp[nt], fd, bf); mma16816(dp[nt] + 4, fd, bf + 2);
                    mma16816(dq[nt], fe, bf); mma16816(dq[nt] + 4, fe, bf + 2);
                }
            }

            // pipelined layer-1 for next step, fills accumulator-drain latency
            if (jj + 1 < SPC) {
                const float tkn = t - dt * (float)(j);   // j+1 >= 1 always
                layer1(smem, ss, W1, b1, tile, m0, gtid, NSTEPS - (j + 1), tkn);
            }

            const float* w4r1 = g_W4T + nb1 * 128;
            const float* w4r2 = g_W4T + nb2 * 128;
            float pu1 = 0.f, pp1 = 0.f, pq1 = 0.f, pu2 = 0.f, pp2 = 0.f, pq2 = 0.f;
#pragma unroll
            for (int nt = 0; nt < 2; nt++) {
                const int j0c = nbase + nt * 16 + jc;
                float h[8], hd[8], he[8];
#pragma unroll
                for (int e = 0; e < 8; e++) chain(dz[nt][e], dp[nt][e], dq[nt][e], h[e], hd[e], he[e]);
                float2 wa1 = __ldg((const float2*)&w4r1[j0c]);
                float2 wb1 = __ldg((const float2*)&w4r1[j0c + 8]);
                float2 wa2 = __ldg((const float2*)&w4r2[j0c]);
                float2 wb2 = __ldg((const float2*)&w4r2[j0c + 8]);
                pp1 += hd[0] * wa1.x + hd[1] * wa1.y + hd[4] * wb1.x + hd[5] * wb1.y;
                pq1 += he[0] * wa1.x + he[1] * wa1.y + he[4] * wb1.x + he[5] * wb1.y;
                pp2 += hd[2] * wa2.x + hd[3] * wa2.y + hd[6] * wb2.x + hd[7] * wb2.y;
                pq2 += he[2] * wa2.x + he[3] * wa2.y + he[6] * wb2.x + he[7] * wb2.y;
                if (j == 0) {   // value channel only contributes at the terminal step
                    pu1 += h[0] * wa1.x + h[1] * wa1.y + h[4] * wb1.x + h[5] * wb1.y;
                    pu2 += h[2] * wa2.x + h[3] * wa2.y + h[6] * wb2.x + h[7] * wb2.y;
                }
            }
#pragma unroll
            for (int off = 1; off <= 2; off <<= 1) {
                pp1 += __shfl_xor_sync(0xffffffffu, pp1, off);
                pq1 += __shfl_xor_sync(0xffffffffu, pq1, off);
                pp2 += __shfl_xor_sync(0xffffffffu, pp2, off);
                pq2 += __shfl_xor_sync(0xffffffffu, pq2, off);
            }
            if (j == 0) {
#pragma unroll
                for (int off = 1; off <= 2; off <<= 1) {
                    pu1 += __shfl_xor_sync(0xffffffffu, pu1, off);
                    pu2 += __shfl_xor_sync(0xffffffffu, pu2, off);
                }
            }
            if ((lane & 3) == 0) {
                float c1 = -fmaf(pp1, dB1, pq1 * halfdt);
                float c2 = -fmaf(pp2, dB2, pq2 * halfdt);
                if (j == 0) {
                    c1 += pu1 + (nq == 0 ? smf[IB4 + nb1] : 0.f);
                    c2 += pu2 + (nq == 0 ? smf[IB4 + nb2] : 0.f);
                }
                acc1 += c1;
                acc2 += c2;
            }
        }
        gbar(slab);      // next A0 ready
    }

    // one-time combine across the 4 col-quarters (deterministic order)
    if ((lane & 3) == 0) {
        smf[ISRED + r1 * 4 + nq] = acc1;
        smf[ISRED + r2 * 4 + nq] = acc2;
    }
    gbar(slab);
    if (nq == 0 && lane < 16) {
        int r = m0 + lane;
        float4 v = *(const float4*)&smf[ISRED + r * 4];
        g_partial[grp * B2 + tile * TILE + r] = (v.x + v.y) + (v.z + v.w);
    }
}

__global__ void bsde_final(const float* __restrict__ ss, float* __restrict__ out)
{
    int b = blockIdx.x * 256 + threadIdx.x;
    if (b >= B2) return;
    float u = 0.0f;
#pragma unroll
    for (int g = 0; g < GROUPS; g++) u += g_partial[g * B2 + b];
    out[b] = u;
    float s0 = ss[b * NP1];
    out[B2 + b] = 3.9894228040143274f * expf(-500000.0f * (s0 * s0));
}

extern "C" void kernel_launch(void* const* d_in, const int* in_sizes, int n_in,
                              void* d_out, int out_size)
{
    const float* W1 = (const float*)d_in[0];
    const float* b1 = (const float*)d_in[1];
    const float* W2 = (const float*)d_in[2];
    const float* b2 = (const float*)d_in[3];
    const float* W3 = (const float*)d_in[4];
    const float* b3 = (const float*)d_in[5];
    const float* W4 = (const float*)d_in[6];
    const float* b4 = (const float*)d_in[7];
    const int* sn = (const int*)d_in[8];
    const float* ss = (const float*)d_in[9];
    const float* sdB = (const float*)d_in[10];
    const float* tptr = (const float*)d_in[11];
    float* out = (float*)d_out;

    cudaFuncSetAttribute(bsde_main, cudaFuncAttributeMaxDynamicSharedMemorySize, SMEM_BYTES);

    w4t_init<<<50, 256>>>(W4);
    bsde_main<<<NTILES * GROUPS, THREADS, SMEM_BYTES>>>(W1, b1, W2, b2, W3, b3, b4,
                                                        sn, ss, sdB, tptr);
    bsde_final<<<16, 256>>>(ss, out);
}

// round 17
// speedup vs baseline: 1.1196x; 1.1196x over previous
#include <cuda_runtime.h>
#include <cuda_fp16.h>
#include <cstdint>

#define NSTEPS 64
#define NP1 65
#define B2 4096
#define TILE 64
#define THREADS 512
#define SPC 4
#define GROUPS (NSTEPS / SPC)     // 16
#define NTILES (B2 / TILE)        // 64

// ---- smem byte offsets ----
#define OFF_W2HI 0
#define OFF_W3HI 32768
#define OFF_A0H  65536
#define OFF_A0D  81920
#define OFF_A0E  98304
#define OFF_A1H  114688
#define OFF_A1D  131072
#define OFF_A1E  147456
#define OFF_B2   163840
#define OFF_B3   164352
#define OFF_B4   164864
#define OFF_SRED 165376
#define SMEM_BYTES 166912

#define IB2   (OFF_B2 >> 2)
#define IB3   (OFF_B3 >> 2)
#define IB4   (OFF_B4 >> 2)
#define ISRED (OFF_SRED >> 2)

__device__ float g_partial[GROUPS * B2];
__device__ float g_W4T[100 * 128];

// hardware tanh (MUFU.TANH): 1 MUFU op vs EX2+RCP+FMAs; abs err ~5e-4,
// same order as the fp16 activation quantization already present.
static __device__ __forceinline__ float tanh_fast(float x) {
    float r;
    asm("tanh.approx.f32 %0, %1;" : "=f"(r) : "f"(x));
    return r;
}
static __device__ __forceinline__ uint32_t swzb(uint32_t r, uint32_t cb) {
    return ((r << 8) + cb) ^ ((r & 7) << 4);
}
static __device__ __forceinline__ uint32_t packh2(float lo, float hi) {
    uint32_t r; asm("cvt.rn.f16x2.f32 %0,%1,%2;" : "=r"(r) : "f"(hi), "f"(lo)); return r;
}
static __device__ __forceinline__ void ldsm4(uint32_t* r, uint32_t a) {
    asm volatile("ldmatrix.sync.aligned.m8n8.x4.shared.b16 {%0,%1,%2,%3},[%4];"
        : "=r"(r[0]), "=r"(r[1]), "=r"(r[2]), "=r"(r[3]) : "r"(a));
}
static __device__ __forceinline__ void mma16816(float* d, const uint32_t* a, const uint32_t* b) {
    asm volatile("mma.sync.aligned.m16n8k16.row.col.f32.f16.f16.f32 "
        "{%0,%1,%2,%3},{%4,%5,%6,%7},{%8,%9},{%0,%1,%2,%3};"
        : "+f"(d[0]), "+f"(d[1]), "+f"(d[2]), "+f"(d[3])
        : "r"(a[0]), "r"(a[1]), "r"(a[2]), "r"(a[3]), "r"(b[0]), "r"(b[1]));
}
static __device__ __forceinline__ void chain(float z, float p, float q,
                                             float& h, float& d, float& e) {
    h = tanh_fast(z);
    float g = 1.0f - h * h;
    d = g * p;
    e = fmaf(g, q, -2.0f * h * d * p);
}
// group barrier: the 4 warps of one sample slab (one warp per SMSP), ids 1..4
static __device__ __forceinline__ void gbar(int slab) {
    asm volatile("bar.sync %0, 128;" :: "r"(slab + 1) : "memory");
}

__global__ void w4t_init(const float* __restrict__ W4) {
    int i = blockIdx.x * 256 + threadIdx.x;
    if (i < 12800) {
        int n = i >> 7, k = i & 127;
        g_W4T[i] = W4[k * 100 + n];
    }
}

// layer-1 forward-mode for one slab's 16 rows -> A0 (fp16, swizzled).
static __device__ __forceinline__ void layer1(
    char* smem, const float* __restrict__ ss,
    const float* __restrict__ W1, const float* __restrict__ b1,
    int tile, int m0, int gtid, int scol, float tk)
{
#pragma unroll
    for (int it = 0; it < 8; it++) {
        int i = gtid + it * 128;
        int r = m0 + (i >> 6), c0 = (i & 63) * 2;
        float s = __ldg(&ss[(tile * TILE + r) * NP1 + scol]);
        float2 w1s = __ldg((const float2*)&W1[c0]);
        float2 w1t = __ldg((const float2*)&W1[128 + c0]);
        float2 b1v = __ldg((const float2*)&b1[c0]);
        float z0 = fmaf(s, w1s.x, fmaf(tk, w1t.x, b1v.x));
        float z1 = fmaf(s, w1s.y, fmaf(tk, w1t.y, b1v.y));
        float h0 = tanh_fast(z0), h1 = tanh_fast(z1);
        float g0 = 1.f - h0 * h0, g1 = 1.f - h1 * h1;
        float d0 = g0 * w1s.x, d1 = g1 * w1s.y;
        float e0 = -2.f * h0 * d0 * w1s.x, e1 = -2.f * h1 * d1 * w1s.y;
        uint32_t o = swzb((uint32_t)r, (uint32_t)(c0 * 2));
        *(uint32_t*)(smem + OFF_A0H + o) = packh2(h0, h1);
        *(uint32_t*)(smem + OFF_A0D + o) = packh2(d0, d1);
        *(uint32_t*)(smem + OFF_A0E + o) = packh2(e0, e1);
    }
}

__global__ __launch_bounds__(THREADS, 1)
void bsde_main(const float* __restrict__ W1, const float* __restrict__ b1,
               const float* __restrict__ W2, const float* __restrict__ b2f,
               const float* __restrict__ W3, const float* __restrict__ b3f,
               const float* __restrict__ b4f,
               const int* __restrict__ sn, const float* __restrict__ ss,
               const float* __restrict__ sdB, const float* __restrict__ tptr)
{
    extern __shared__ char smem[];
    uint32_t sb = (uint32_t)__cvta_generic_to_shared(smem);
    float* smf = (float*)smem;
    const int tid = threadIdx.x;
    const int lane = tid & 31;
    const int w = tid >> 5;
    // TRANSPOSED mapping: slab spreads its 4 warps across the 4 SMSPs.
    const int slab = w >> 2;       // sample slab (m16)
    const int nq = w & 3;          // col quarter (n32) == SMSP id
    const int m0 = slab * 16;
    const int nbase = nq * 32;
    const int gtid = nq * 32 + lane;

    for (int i = tid; i < 128 * 128; i += THREADS) {
        int k = i >> 7, j = i & 127;
        uint32_t o = swzb((uint32_t)j, (uint32_t)(k * 2));
        *(__half*)(smem + OFF_W2HI + o) = __float2half_rn(W2[i]);
        *(__half*)(smem + OFF_W3HI + o) = __float2half_rn(W3[i]);
    }
    if (tid < 128) {
        smf[IB2 + tid] = b2f[tid];
        smf[IB3 + tid] = b3f[tid];
        smf[IB4 + tid] = (tid < 100) ? b4f[tid] : 0.0f;
    }

    const int tile = blockIdx.x & (NTILES - 1);
    const int grp = blockIdx.x >> 6;
    const int j0 = grp * SPC;
    const float t = *tptr;
    const float dt = t / (float)NSTEPS;
    const float halfdt = 0.5f * dt;
    float acc = 0.0f;

    const uint32_t rowA = (uint32_t)(m0 + (lane & 7) + ((lane >> 3) & 1) * 8);
    const uint32_t colA = (uint32_t)(((lane >> 4) & 1) * 16);
    const uint32_t rbA  = rowA << 8;
    const uint32_t xA   = (rowA & 7) << 4;
    const uint32_t rowB4 = (uint32_t)((lane & 7) + ((lane >> 4) & 1) * 8);
    const uint32_t colB4 = (uint32_t)(((lane >> 3) & 1) * 16);
    const uint32_t xB4   = (uint32_t)(lane & 7) << 4;

    const int r1 = m0 + (lane >> 2);
    const int r2 = r1 + 8;
    const int jc = 2 * (lane & 3);

    __syncthreads();   // weights + biases ready

    // prologue: layer-1 for first step
    {
        const float tk0 = (j0 == 0) ? t : (t - dt * (float)(j0 - 1));
        layer1(smem, ss, W1, b1, tile, m0, gtid, NSTEPS - j0, tk0);
    }
    gbar(slab);

    for (int jj = 0; jj < SPC; jj++) {
        const int j = j0 + jj;

        const float dB1 = sdB[(tile * TILE + r1) * NSTEPS + (NSTEPS - 1 - j)];
        const float dB2 = sdB[(tile * TILE + r2) * NSTEPS + (NSTEPS - 1 - j)];
        const int nb1 = sn[(tile * TILE + r1) * NP1 + (NSTEPS - j)];
        const int nb2 = sn[(tile * TILE + r2) * NP1 + (NSTEPS - j)];

        // ================= layer 2: A0 @ W2 -> A1 =================
        {
            float dz[2][8], dp[2][8], dq[2][8];
#pragma unroll
            for (int nt = 0; nt < 2; nt++) {
                const int j0c = nbase + nt * 16 + jc;
                float2 bj = *(const float2*)&smf[IB2 + j0c];
                float2 bj8 = *(const float2*)&smf[IB2 + j0c + 8];
                dz[nt][0] = bj.x; dz[nt][1] = bj.y; dz[nt][2] = bj.x; dz[nt][3] = bj.y;
                dz[nt][4] = bj8.x; dz[nt][5] = bj8.y; dz[nt][6] = bj8.x; dz[nt][7] = bj8.y;
#pragma unroll
                for (int e = 0; e < 8; e++) { dp[nt][e] = 0.f; dq[nt][e] = 0.f; }
            }
            const uint32_t aHb = sb + OFF_A0H + rbA, aDb = sb + OFF_A0D + rbA, aEb = sb + OFF_A0E + rbA;
            const uint32_t wBase = sb + OFF_W2HI + (((uint32_t)nbase + rowB4) << 8);
#pragma unroll
            for (int k = 0; k < 8; k++) {
                const uint32_t oA = (colA + 32u * k) ^ xA;
                const uint32_t oB = (colB4 + 32u * k) ^ xB4;
                uint32_t fa[4], fd[4], fe[4];
                ldsm4(fa, aHb + oA); ldsm4(fd, aDb + oA); ldsm4(fe, aEb + oA);
#pragma unroll
                for (int nt = 0; nt < 2; nt++) {
                    uint32_t bf[4];
                    ldsm4(bf, wBase + ((uint32_t)(nt * 16) << 8) + oB);
                    mma16816(dz[nt], fa, bf); mma16816(dz[nt] + 4, fa, bf + 2);
                    mma16816(dp[nt], fd, bf); mma16816(dp[nt] + 4, fd, bf + 2);
                    mma16816(dq[nt], fe, bf); mma16816(dq[nt] + 4, fe, bf + 2);
                }
            }
#pragma unroll
            for (int nt = 0; nt < 2; nt++) {
                const int j0c = nbase + nt * 16 + jc;
                float h[8], hd[8], he[8];
#pragma unroll
                for (int e = 0; e < 8; e++) chain(dz[nt][e], dp[nt][e], dq[nt][e], h[e], hd[e], he[e]);
                uint32_t o1 = swzb((uint32_t)r1, (uint32_t)(j0c * 2));
                uint32_t o2 = swzb((uint32_t)r2, (uint32_t)(j0c * 2));
                uint32_t o3 = swzb((uint32_t)r1, (uint32_t)((j0c + 8) * 2));
                uint32_t o4 = swzb((uint32_t)r2, (uint32_t)((j0c + 8) * 2));
                *(uint32_t*)(smem + OFF_A1H + o1) = packh2(h[0], h[1]);
                *(uint32_t*)(smem + OFF_A1H + o2) = packh2(h[2], h[3]);
                *(uint32_t*)(smem + OFF_A1H + o3) = packh2(h[4], h[5]);
                *(uint32_t*)(smem + OFF_A1H + o4) = packh2(h[6], h[7]);
                *(uint32_t*)(smem + OFF_A1D + o1) = packh2(hd[0], hd[1]);
                *(uint32_t*)(smem + OFF_A1D + o2) = packh2(hd[2], hd[3]);
                *(uint32_t*)(smem + OFF_A1D + o3) = packh2(hd[4], hd[5]);
                *(uint32_t*)(smem + OFF_A1D + o4) = packh2(hd[6], hd[7]);
                *(uint32_t*)(smem + OFF_A1E + o1) = packh2(he[0], he[1]);
                *(uint32_t*)(smem + OFF_A1E + o2) = packh2(he[2], he[3]);
                *(uint32_t*)(smem + OFF_A1E + o3) = packh2(he[4], he[5]);
                *(uint32_t*)(smem + OFF_A1E + o4) = packh2(he[6], he[7]);
            }
        }
        gbar(slab);      // A1 ready; A0 now dead -> safe to refill below

        // ================= layer 3 (A1 @ W3) + pipelined layer-1(j+1) + layer 4 =================
        {
            float dz[2][8], dp[2][8], dq[2][8];
#pragma unroll
            for (int nt = 0; nt < 2; nt++) {
                const int j0c = nbase + nt * 16 + jc;
                float2 bj = *(const float2*)&smf[IB3 + j0c];
                float2 bj8 = *(const float2*)&smf[IB3 + j0c + 8];
                dz[nt][0] = bj.x; dz[nt][1] = bj.y; dz[nt][2] = bj.x; dz[nt][3] = bj.y;
                dz[nt][4] = bj8.x; dz[nt][5] = bj8.y; dz[nt][6] = bj8.x; dz[nt][7] = bj8.y;
#pragma unroll
                for (int e = 0; e < 8; e++) { dp[nt][e] = 0.f; dq[nt][e] = 0.f; }
            }
            const uint32_t aHb = sb + OFF_A1H + rbA, aDb = sb + OFF_A1D + rbA, aEb = sb + OFF_A1E + rbA;
            const uint32_t wBase = sb + OFF_W3HI + (((uint32_t)nbase + rowB4) << 8);
#pragma unroll
            for (int k = 0; k < 8; k++) {
                const uint32_t oA = (colA + 32u * k) ^ xA;
                const uint32_t oB = (colB4 + 32u * k) ^ xB4;
                uint32_t fa[4], fd[4], fe[4];
                ldsm4(fa, aHb + oA); ldsm4(fd, aDb + oA); ldsm4(fe, aEb + oA);
#pragma unroll
                for (int nt = 0; nt < 2; nt++) {
                    uint32_t bf[4];
                    ldsm4(bf, wBase + ((uint32_t)(nt * 16) << 8) + oB);
                    mma16816(dz[nt], fa, bf); mma16816(dz[nt] + 4, fa, bf + 2);
                    mma16816(dp[nt], fd, bf); mma16816(dp[nt] + 4, fd, bf + 2);
                    mma16816(dq[nt], fe, bf); mma16816(dq[nt] + 4, fe, bf + 2);
                }
            }

            // pipelined layer-1 for next step, fills accumulator-drain latency
            if (jj + 1 < SPC) {
                const float tkn = t - dt * (float)(j);   // j+1 >= 1 always
                layer1(smem, ss, W1, b1, tile, m0, gtid, NSTEPS - (j + 1), tkn);
            }

            const float* w4r1 = g_W4T + nb1 * 128;
            const float* w4r2 = g_W4T + nb2 * 128;
            float pu1 = 0.f, pp1 = 0.f, pq1 = 0.f, pu2 = 0.f, pp2 = 0.f, pq2 = 0.f;
#pragma unroll
            for (int nt = 0; nt < 2; nt++) {
                const int j0c = nbase + nt * 16 + jc;
                float h[8], hd[8], he[8];
#pragma unroll
                for (int e = 0; e < 8; e++) chain(dz[nt][e], dp[nt][e], dq[nt][e], h[e], hd[e], he[e]);
                float2 wa1 = __ldg((const float2*)&w4r1[j0c]);
                float2 wb1 = __ldg((const float2*)&w4r1[j0c + 8]);
                float2 wa2 = __ldg((const float2*)&w4r2[j0c]);
                float2 wb2 = __ldg((const float2*)&w4r2[j0c + 8]);
                pu1 += h[0] * wa1.x + h[1] * wa1.y + h[4] * wb1.x + h[5] * wb1.y;
                pp1 += hd[0] * wa1.x + hd[1] * wa1.y + hd[4] * wb1.x + hd[5] * wb1.y;
                pq1 += he[0] * wa1.x + he[1] * wa1.y + he[4] * wb1.x + he[5] * wb1.y;
                pu2 += h[2] * wa2.x + h[3] * wa2.y + h[6] * wb2.x + h[7] * wb2.y;
                pp2 += hd[2] * wa2.x + hd[3] * wa2.y + hd[6] * wb2.x + hd[7] * wb2.y;
                pq2 += he[2] * wa2.x + he[3] * wa2.y + he[6] * wb2.x + he[7] * wb2.y;
            }
#pragma unroll
            for (int off = 1; off <= 2; off <<= 1) {
                pu1 += __shfl_xor_sync(0xffffffffu, pu1, off);
                pp1 += __shfl_xor_sync(0xffffffffu, pp1, off);
                pq1 += __shfl_xor_sync(0xffffffffu, pq1, off);
                pu2 += __shfl_xor_sync(0xffffffffu, pu2, off);
                pp2 += __shfl_xor_sync(0xffffffffu, pp2, off);
                pq2 += __shfl_xor_sync(0xffffffffu, pq2, off);
            }
            if ((lane & 3) == 0) {
                float c1 = -fmaf(pp1, dB1, pq1 * halfdt);
                float c2 = -fmaf(pp2, dB2, pq2 * halfdt);
                if (j == 0) {
                    c1 += pu1 + (nq == 0 ? smf[IB4 + nb1] : 0.f);
                    c2 += pu2 + (nq == 0 ? smf[IB4 + nb2] : 0.f);
                }
                smf[ISRED + r1 * 4 + nq] = c1;
                smf[ISRED + r2 * 4 + nq] = c2;
            }
        }
        gbar(slab);      // SRED + next A0 ready

        if (nq == 0 && lane < 16) {
            int r = m0 + lane;
            float4 v = *(const float4*)&smf[ISRED + r * 4];
            acc += (v.x + v.y) + (v.z + v.w);
        }
    }

    if (nq == 0 && lane < 16)
        g_partial[grp * B2 + tile * TILE + m0 + lane] = acc;
}

__global__ void bsde_final(const float* __restrict__ ss, float* __restrict__ out)
{
    int b = blockIdx.x * 256 + threadIdx.x;
    if (b >= B2) return;
    float u = 0.0f;
#pragma unroll
    for (int g = 0; g < GROUPS; g++) u += g_partial[g * B2 + b];
    out[b] = u;
    float s0 = ss[b * NP1];
    out[B2 + b] = 3.9894228040143274f * expf(-500000.0f * (s0 * s0));
}

extern "C" void kernel_launch(void* const* d_in, const int* in_sizes, int n_in,
                              void* d_out, int out_size)
{
    const float* W1 = (const float*)d_in[0];
    const float* b1 = (const float*)d_in[1];
    const float* W2 = (const float*)d_in[2];
    const float* b2 = (const float*)d_in[3];
    const float* W3 = (const float*)d_in[4];
    const float* b3 = (const float*)d_in[5];
    const float* W4 = (const float*)d_in[6];
    const float* b4 = (const float*)d_in[7];
    const int* sn = (const int*)d_in[8];
    const float* ss = (const float*)d_in[9];
    const float* sdB = (const float*)d_in[10];
    const float* tptr = (const float*)d_in[11];
    float* out = (float*)d_out;

    cudaFuncSetAttribute(bsde_main, cudaFuncAttributeMaxDynamicSharedMemorySize, SMEM_BYTES);

    w4t_init<<<50, 256>>>(W4);
    bsde_main<<<NTILES * GROUPS, THREADS, SMEM_BYTES>>>(W1, b1, W2, b2, W3, b3, b4,
                                                        sn, ss, sdB, tptr);
    bsde_final<<<16, 256>>>(ss, out);
}